// round 1
// baseline (speedup 1.0000x reference)
#include <cuda_runtime.h>
#include <cuda_bf16.h>
#include <math.h>

// ---------------- problem constants ----------------
#define T_TOK 2048
#define HID   2048
#define NH    32
#define NKV   8
#define HD    64
#define GROUPS 4
#define EPSV  1e-6f
// softmax scale = 1/sqrt(64)
#define SM_SCALE 0.125f

// ---------------- scratch (device globals; no cudaMalloc allowed) ----------------
__device__ float g_q[T_TOK * NH * HD];     // [2048, 2048]
__device__ float g_k[T_TOK * NKV * HD];    // [2048, 512]
__device__ float g_v[T_TOK * NKV * HD];    // [2048, 512]
__device__ float g_o[T_TOK * NH * HD];     // [2048, 2048] attention out (pre-Wo)
__device__ float g_cos[T_TOK * (HD / 2)];  // [2048, 32]
__device__ float g_sin[T_TOK * (HD / 2)];

// ============================================================================
// Shared 64x64x16 SGEMM tile (256 threads, 4x4 per thread).
// A is [M,2048] row-major (lda=2048). K loop covers kTotal; for k>=2048 it
// switches to (A2,B2) with row offset k-2048 (used for the hidden+mu fusion).
// ============================================================================
__device__ __forceinline__ void sgemm64(
    const float* __restrict__ A1, const float* __restrict__ A2,
    const float* __restrict__ B1, const float* __restrict__ B2,
    int ldb, float* __restrict__ C, int ldc, int nloc, int kTotal)
{
    const int m0 = blockIdx.y * 64;
    const int t  = threadIdx.x;
    const int tx = t & 15;
    const int ty = t >> 4;

    __shared__ float As[16][64];   // [k][m]
    __shared__ float Bs[16][64];   // [k][n]

    float acc[4][4];
#pragma unroll
    for (int i = 0; i < 4; i++)
#pragma unroll
        for (int j = 0; j < 4; j++) acc[i][j] = 0.0f;

    const int am = t >> 2;          // 0..63  (m within tile)
    const int ak = (t & 3) * 4;     // 0,4,8,12 (k within tile)
    const int bk = t >> 4;          // 0..15  (k within tile)
    const int bn = (t & 15) * 4;    // 0..60  (n within tile)

    for (int k0 = 0; k0 < kTotal; k0 += 16) {
        const float* A = A1;
        const float* B = B1;
        int koff = k0;
        if (k0 >= 2048) { A = A2; B = B2; koff = k0 - 2048; }

        float4 a4 = *(const float4*)&A[(m0 + am) * 2048 + koff + ak];
        float4 b4 = *(const float4*)&B[(size_t)(koff + bk) * ldb + nloc + bn];

        __syncthreads();
        As[ak + 0][am] = a4.x;
        As[ak + 1][am] = a4.y;
        As[ak + 2][am] = a4.z;
        As[ak + 3][am] = a4.w;
        *(float4*)&Bs[bk][bn] = b4;
        __syncthreads();

#pragma unroll
        for (int k = 0; k < 16; k++) {
            float4 av = *(const float4*)&As[k][ty * 4];
            float4 bv = *(const float4*)&Bs[k][tx * 4];
            float a[4] = {av.x, av.y, av.z, av.w};
            float b[4] = {bv.x, bv.y, bv.z, bv.w};
#pragma unroll
            for (int i = 0; i < 4; i++)
#pragma unroll
                for (int j = 0; j < 4; j++)
                    acc[i][j] = fmaf(a[i], b[j], acc[i][j]);
        }
    }

#pragma unroll
    for (int i = 0; i < 4; i++)
#pragma unroll
        for (int j = 0; j < 4; j++)
            C[(size_t)(m0 + ty * 4 + i) * ldc + nloc + tx * 4 + j] = acc[i][j];
}

// ---- QKV projection: q = hidden@Wq + mu@Wmq (and k,v analogues), fused as K=4096 ----
// grid: (48, 32)  — columns: [0,2048)=q, [2048,2560)=k, [2560,3072)=v
__global__ void qkv_gemm_kernel(
    const float* __restrict__ hidden, const float* __restrict__ mu,
    const float* __restrict__ Wq, const float* __restrict__ Wk, const float* __restrict__ Wv,
    const float* __restrict__ Wmq, const float* __restrict__ Wmk, const float* __restrict__ Wmv)
{
    const int n0 = blockIdx.x * 64;
    const float* B1;
    const float* B2;
    float* C;
    int ldb, nloc;
    if (n0 < 2048)      { B1 = Wq; B2 = Wmq; C = g_q; ldb = 2048; nloc = n0;        }
    else if (n0 < 2560) { B1 = Wk; B2 = Wmk; C = g_k; ldb = 512;  nloc = n0 - 2048; }
    else                { B1 = Wv; B2 = Wmv; C = g_v; ldb = 512;  nloc = n0 - 2560; }
    sgemm64(hidden, mu, B1, B2, ldb, C, ldb, nloc, 4096);
}

// ---- output projection: out = g_o @ Wo ----
__global__ void out_gemm_kernel(const float* __restrict__ Wo, float* __restrict__ out)
{
    sgemm64(g_o, g_o, Wo, Wo, 2048, out, 2048, blockIdx.x * 64, 2048);
}

// ============================================================================
// RoPE tables in double precision (one-time, tiny)
// ============================================================================
__global__ void rope_table_kernel(const int* __restrict__ positions)
{
    int idx = blockIdx.x * blockDim.x + threadIdx.x;   // t*32 + i
    if (idx >= T_TOK * 32) return;
    int t = idx >> 5;
    int i = idx & 31;
    double invf = pow(10000.0, -(double)i / 32.0);
    double fd   = (double)positions[t] * invf;
    g_cos[idx] = (float)cos(fd);
    g_sin[idx] = (float)sin(fd);
}

// ============================================================================
// Fused RMSNorm + RoPE for q (32 heads) and k (8 heads). One warp per (t, head).
// Lane l owns x[l] and x[l+32]; RoPE pair (l, l+32) shares cos/sin index l.
// ============================================================================
__global__ void norm_rope_kernel(const float* __restrict__ qw,
                                 const float* __restrict__ kw,
                                 const int* /*positions (tables precomputed)*/)
{
    int warpId = blockIdx.x * (blockDim.x >> 5) + (threadIdx.x >> 5);
    int lane   = threadIdx.x & 31;
    if (warpId >= T_TOK * (NH + NKV)) return;
    int t  = warpId / (NH + NKV);
    int hh = warpId % (NH + NKV);

    float* buf;
    int ld, col;
    const float* w;
    if (hh < NH) { buf = g_q; ld = NH * HD;  col = hh * HD;        w = qw; }
    else         { buf = g_k; ld = NKV * HD; col = (hh - NH) * HD; w = kw; }

    float x0 = buf[(size_t)t * ld + col + lane];
    float x1 = buf[(size_t)t * ld + col + 32 + lane];
    float ss = x0 * x0 + x1 * x1;
#pragma unroll
    for (int o = 16; o > 0; o >>= 1) ss += __shfl_xor_sync(0xffffffff, ss, o);
    float inv = rsqrtf(ss * (1.0f / 64.0f) + EPSV);
    x0 *= inv * w[lane];
    x1 *= inv * w[lane + 32];

    float c = g_cos[t * 32 + lane];
    float s = g_sin[t * 32 + lane];
    buf[(size_t)t * ld + col + lane]      = x0 * c - x1 * s;
    buf[(size_t)t * ld + col + 32 + lane] = x1 * c + x0 * s;
}

// ============================================================================
// Causal flash attention. grid: (qTiles=32, NH=32), block 256.
// Per block: 64 queries x full head_dim. Online softmax over lower-tri key tiles.
// ============================================================================
#define FLD 65                                   // padded row stride in smem
#define FLASH_SMEM ((4 * 64 * FLD + 3 * 64) * (int)sizeof(float))

__global__ void flash_kernel()
{
    extern __shared__ float sm[];
    float* Qs   = sm;
    float* Ks   = sm + 64 * FLD;
    float* Vs   = sm + 2 * 64 * FLD;
    float* Ss   = sm + 3 * 64 * FLD;
    float* mrow = sm + 4 * 64 * FLD;
    float* lrow = mrow + 64;
    float* arow = lrow + 64;

    const int qt   = blockIdx.x;
    const int h    = blockIdx.y;
    const int kvh  = h >> 2;              // GQA: groups of 4 share a kv head
    const int t    = threadIdx.x;
    const int tx   = t & 15;
    const int ty   = t >> 4;
    const int lane = t & 31;
    const int warp = t >> 5;
    const int q0   = qt * 64;

    // load Q tile [64 x 64]
#pragma unroll
    for (int u = 0; u < 16; u++) {
        int e = u * 256 + t;
        int r = e >> 6, c = e & 63;
        Qs[r * FLD + c] = g_q[(size_t)(q0 + r) * (NH * HD) + h * HD + c];
    }
    if (t < 64) { mrow[t] = -1e30f; lrow[t] = 0.0f; }

    float acc[4][4];
#pragma unroll
    for (int i = 0; i < 4; i++)
#pragma unroll
        for (int j = 0; j < 4; j++) acc[i][j] = 0.0f;

    __syncthreads();

    for (int kt = 0; kt <= qt; kt++) {
        // load K and V tiles (prev iter's Ss/Vs reads finished at last sync)
#pragma unroll
        for (int u = 0; u < 16; u++) {
            int e = u * 256 + t;
            int r = e >> 6, c = e & 63;
            size_t gi = (size_t)(kt * 64 + r) * (NKV * HD) + kvh * HD + c;
            Ks[r * FLD + c] = g_k[gi];
            Vs[r * FLD + c] = g_v[gi];
        }
        __syncthreads();

        // S = Q @ K^T (each thread 4x4)
        float s[4][4];
#pragma unroll
        for (int i = 0; i < 4; i++)
#pragma unroll
            for (int j = 0; j < 4; j++) s[i][j] = 0.0f;

        for (int d = 0; d < 64; d++) {
            float a[4], b[4];
#pragma unroll
            for (int i = 0; i < 4; i++) a[i] = Qs[(ty * 4 + i) * FLD + d];
#pragma unroll
            for (int j = 0; j < 4; j++) b[j] = Ks[(tx * 4 + j) * FLD + d];
#pragma unroll
            for (int i = 0; i < 4; i++)
#pragma unroll
                for (int j = 0; j < 4; j++)
                    s[i][j] = fmaf(a[i], b[j], s[i][j]);
        }

        // scale + causal mask (only diagonal tile needs masking), write to smem
        const bool diag = (kt == qt);
#pragma unroll
        for (int i = 0; i < 4; i++)
#pragma unroll
            for (int j = 0; j < 4; j++) {
                float v = s[i][j] * SM_SCALE;
                if (diag && (tx * 4 + j) > (ty * 4 + i)) v = -1e30f;
                Ss[(ty * 4 + i) * FLD + tx * 4 + j] = v;
            }
        __syncthreads();

        // online softmax: warp w handles rows [8w, 8w+8)
#pragma unroll
        for (int rr = 0; rr < 8; rr++) {
            int row = warp * 8 + rr;
            float s0 = Ss[row * FLD + lane];
            float s1 = Ss[row * FLD + 32 + lane];
            float mx = fmaxf(s0, s1);
#pragma unroll
            for (int o = 16; o > 0; o >>= 1) mx = fmaxf(mx, __shfl_xor_sync(0xffffffff, mx, o));
            float mprev = mrow[row];
            float mnew  = fmaxf(mprev, mx);
            float p0 = __expf(s0 - mnew);
            float p1 = __expf(s1 - mnew);
            Ss[row * FLD + lane]      = p0;
            Ss[row * FLD + 32 + lane] = p1;
            float sum = p0 + p1;
#pragma unroll
            for (int o = 16; o > 0; o >>= 1) sum += __shfl_xor_sync(0xffffffff, sum, o);
            float al = __expf(mprev - mnew);
            __syncwarp();
            if (lane == 0) {
                lrow[row] = lrow[row] * al + sum;
                mrow[row] = mnew;
                arow[row] = al;
            }
        }
        __syncthreads();

        // O = O*alpha + P @ V
#pragma unroll
        for (int i = 0; i < 4; i++) {
            float al = arow[ty * 4 + i];
#pragma unroll
            for (int j = 0; j < 4; j++) acc[i][j] *= al;
        }
        for (int kk = 0; kk < 64; kk++) {
            float p[4], v[4];
#pragma unroll
            for (int i = 0; i < 4; i++) p[i] = Ss[(ty * 4 + i) * FLD + kk];
#pragma unroll
            for (int j = 0; j < 4; j++) v[j] = Vs[kk * FLD + tx * 4 + j];
#pragma unroll
            for (int i = 0; i < 4; i++)
#pragma unroll
                for (int j = 0; j < 4; j++)
                    acc[i][j] = fmaf(p[i], v[j], acc[i][j]);
        }
        __syncthreads();   // lrow/Ss/Vs stable before next iteration overwrites
    }

    // normalize and write
#pragma unroll
    for (int i = 0; i < 4; i++) {
        float inv = 1.0f / lrow[ty * 4 + i];
#pragma unroll
        for (int j = 0; j < 4; j++)
            g_o[(size_t)(q0 + ty * 4 + i) * (NH * HD) + h * HD + tx * 4 + j] = acc[i][j] * inv;
    }
}

// ============================================================================
// launch
// ============================================================================
extern "C" void kernel_launch(void* const* d_in, const int* in_sizes, int n_in,
                              void* d_out, int out_size)
{
    const float* hidden = (const float*)d_in[0];
    const float* mu     = (const float*)d_in[1];
    const float* Wq     = (const float*)d_in[2];
    const float* Wk     = (const float*)d_in[3];
    const float* Wv     = (const float*)d_in[4];
    const float* Wo     = (const float*)d_in[5];
    const float* Wmq    = (const float*)d_in[6];
    const float* Wmk    = (const float*)d_in[7];
    const float* Wmv    = (const float*)d_in[8];
    const float* qnw    = (const float*)d_in[9];
    const float* knw    = (const float*)d_in[10];
    const int*   pos    = (const int*)d_in[11];
    float* out          = (float*)d_out;

    cudaFuncSetAttribute(flash_kernel, cudaFuncAttributeMaxDynamicSharedMemorySize, FLASH_SMEM);

    // QKV projection (fused hidden+mu, K=4096; N regions: q|k|v)
    qkv_gemm_kernel<<<dim3(48, 32), 256>>>(hidden, mu, Wq, Wk, Wv, Wmq, Wmk, Wmv);

    // RoPE tables (double precision, tiny)
    rope_table_kernel<<<(T_TOK * 32 + 255) / 256, 256>>>(pos);

    // RMSNorm + RoPE on q and k heads (one warp per (token, head))
    norm_rope_kernel<<<(T_TOK * (NH + NKV) + 7) / 8, 256>>>(qnw, knw, pos);

    // causal flash attention
    flash_kernel<<<dim3(T_TOK / 64, NH), 256, FLASH_SMEM>>>();

    // output projection
    out_gemm_kernel<<<dim3(32, 32), 256>>>(Wo, out);
}